// round 15
// baseline (speedup 1.0000x reference)
#include <cuda_runtime.h>
#include <cuda_fp16.h>
#include <cstdint>

#define NROWS   131072
#define DIM     64
#define NE      1024
#define DECAYF  0.99f
#define ONE_M_D 0.01f
#define EPSF    1e-5f

#define OFF_Q    0
#define OFF_DIFF 8388608
#define OFF_IND  8388609
#define OFF_NCS  8519681
#define OFF_NEA  8520705
#define OFF_NE   8586241

#define NGRP 8

// device scratch (statically zero-initialized; k2a/k2b re-zero after use)
__device__ float    g_countP[NGRP][NE];
__device__ float    g_esumP[NGRP][NE * DIM];
__device__ double   g_diff;
__device__ float    g_n;
__device__ uint32_t g_ebH[NE * 32];   // fp16-hi of embed, col-major
__device__ float    g_ebT[NE * DIM];  // transposed fp32 embed [j][k]
__device__ float    g_en[NE];         // ||e_j||^2
__device__ int      g_maxE2i;
__device__ int      g_maxEl2i;

// ------------------------------------------------------------------
__device__ __forceinline__ void mma_f16(float* c, const uint32_t* a, const uint32_t* b) {
    asm volatile(
        "mma.sync.aligned.m16n8k16.row.col.f32.f16.f16.f32 "
        "{%0,%1,%2,%3}, {%4,%5,%6,%7}, {%8,%9}, {%0,%1,%2,%3};"
        : "+f"(c[0]), "+f"(c[1]), "+f"(c[2]), "+f"(c[3])
        : "r"(a[0]), "r"(a[1]), "r"(a[2]), "r"(a[3]),
          "r"(b[0]), "r"(b[1]));
}
__device__ __forceinline__ void ldm4(uint32_t* r, uint32_t addr) {
    asm volatile("ldmatrix.sync.aligned.m8n8.x4.shared.b16 {%0,%1,%2,%3}, [%4];"
        : "=r"(r[0]), "=r"(r[1]), "=r"(r[2]), "=r"(r[3]) : "r"(addr));
}
__device__ __forceinline__ uint32_t h2(float a, float b) {
    __half2 h = __floats2half2_rn(a, b);
    return *(uint32_t*)&h;
}
__device__ __forceinline__ uint32_t smem_u32(const void* p) {
    uint32_t a;
    asm("{ .reg .u64 t; cvta.to.shared.u64 t, %1; cvt.u32.u64 %0, t; }" : "=r"(a) : "l"(p));
    return a;
}
__device__ __forceinline__ void cp16(uint32_t s, const void* g) {
    asm volatile("cp.async.cg.shared.global [%0], [%1], 16;" :: "r"(s), "l"(g));
}
#define CP_COMMIT() asm volatile("cp.async.commit_group;" ::: "memory")
#define CP_WAIT0()  asm volatile("cp.async.wait_group 0;" ::: "memory")

// ------------------------------------------------------------------
// SMEM (32-bit words)
#define WA 68
#define WB 36
#define SM_A    0
#define SM_B0   (64 * WA)                  // 4352
#define SM_B1   (SM_B0 + 128 * WB)         // 8960
#define SM_KEY  SM_B0
#define SM_NORM (SM_B1 + 128 * WB)         // 13568
#define SMEM_WORDS (SM_NORM + 512)         // 14080
#define SMEM_BYTES (SMEM_WORDS * 4)        // 56320

#define BM 64
#define NC 128
#define NCH 8

// ------------------------------------------------------------------
__global__ void k0pre(const float* __restrict__ embed) {
    const int j = blockIdx.x * 128 + threadIdx.x;   // 1024 threads
    float en = 0.0f, el2 = 0.0f;
    #pragma unroll 8
    for (int w = 0; w < 32; w++) {
        float v0 = embed[(2 * w) * NE + j];
        float v1 = embed[(2 * w + 1) * NE + j];
        en = fmaf(v0, v0, fmaf(v1, v1, en));
        uint32_t hw = h2(v0, v1);
        __half2 hh = *(__half2*)&hw;
        float2 f = __half22float2(hh);
        float l0 = v0 - f.x, l1 = v1 - f.y;
        el2 = fmaf(l0, l0, fmaf(l1, l1, el2));
        g_ebH[j * 32 + w] = hw;
        g_ebT[j * 64 + 2 * w]     = v0;
        g_ebT[j * 64 + 2 * w + 1] = v1;
    }
    g_en[j] = en;
    atomicMax(&g_maxE2i,  __float_as_int(en));
    atomicMax(&g_maxEl2i, __float_as_int(el2));
}

// ------------------------------------------------------------------
__global__ void __launch_bounds__(256, 2) k1_main(
    const float* __restrict__ x,
    const float* __restrict__ embed,
    float* __restrict__ out)
{
    extern __shared__ uint32_t smw[];
    uint32_t* As = smw + SM_A;
    float* sKey = (float*)(smw + SM_KEY);
    float* sNh = (float*)(smw + SM_NORM);
    float* sNl = (float*)(smw + SM_NORM + 256);
    const uint32_t smbA  = smem_u32(smw);
    const uint32_t smbB0 = smbA + SM_B0 * 4;
    const uint32_t smbB1 = smbA + SM_B1 * 4;

    const int tid  = threadIdx.x;
    const int wid  = tid >> 5;
    const int lane = tid & 31;
    const int g    = lane >> 2;
    const int q    = lane & 3;
    const int wm   = wid >> 2;
    const int wn   = wid & 3;
    const int rowBase = blockIdx.x * BM;
    const int grp = blockIdx.x & (NGRP - 1);

    // ---- prefetch B chunk 0 ----
    #pragma unroll
    for (int it = 0; it < 4; ++it) {
        const int task = tid + it * 256;
        const int col = task >> 3, part = task & 7;
        cp16(smbB0 + (uint32_t)(col * WB + part * 4) * 4,
             g_ebH + (size_t)col * 32 + part * 4);
    }
    CP_COMMIT();

    // ---- load A: fp16 split + norm partials (4 thr/row) ----
    {
        const int r = tid >> 2, quarter = tid & 3;
        const float4* xg = (const float4*)(x + (size_t)(rowBase + r) * DIM) + quarter * 4;
        uint32_t* dA = As + r * WA + quarter * 8;
        float nh = 0.0f, nl = 0.0f;
        #pragma unroll
        for (int i = 0; i < 4; i++) {
            float4 v = xg[i];
            uint32_t hxy = h2(v.x, v.y), hzw = h2(v.z, v.w);
            __half2 hh0 = *(__half2*)&hxy, hh1 = *(__half2*)&hzw;
            float2 f0 = __half22float2(hh0), f1 = __half22float2(hh1);
            float l00 = v.x - f0.x, l01 = v.y - f0.y;
            float l10 = v.z - f1.x, l11 = v.w - f1.y;
            nh = fmaf(f0.x, f0.x, fmaf(f0.y, f0.y, fmaf(f1.x, f1.x, fmaf(f1.y, f1.y, nh))));
            nl = fmaf(l00, l00, fmaf(l01, l01, fmaf(l10, l10, fmaf(l11, l11, nl))));
            dA[2 * i]          = hxy;
            dA[2 * i + 1]      = hzw;
            dA[32 + 2 * i]     = h2(l00, l01);
            dA[32 + 2 * i + 1] = h2(l10, l11);
        }
        sNh[tid] = nh;
        sNl[tid] = nl;
    }
    __syncthreads();   // A tile visible to ldmatrix

    // ---- preload ALL A-hi fragments into registers (chunk-invariant) ----
    const int r8  = lane & 7;
    const int sel = lane >> 3;
    uint32_t Af[4][2][4];   // [slice][mf][frag]
    {
        uint32_t aAddr[2];
        #pragma unroll
        for (int mf = 0; mf < 2; mf++) {
            const int row = wm * 32 + mf * 16 + r8 + (sel & 1) * 8;
            aAddr[mf] = smbA + (uint32_t)(row * WA + (sel >> 1) * 4) * 4;
        }
        #pragma unroll
        for (int s = 0; s < 4; s++)
            #pragma unroll
            for (int mf = 0; mf < 2; mf++)
                ldm4(Af[s][mf], aAddr[mf] + (uint32_t)(8 * s) * 4);
    }

    const uint32_t bOff0 = (uint32_t)((wn * 32 + r8 + (sel >> 1) * 8) * WB + (sel & 1) * 4) * 4;
    const uint32_t bOff1 = bOff0 + (uint32_t)(16 * WB) * 4;

    // float-packed top-2 keys per slot
    float b1k[4], b2k[4];
    #pragma unroll
    for (int i = 0; i < 4; i++) { b1k[i] = -3.4e38f; b2k[i] = -3.4e38f; }

    for (int c = 0; c < NCH; c++) {
        const int cb = c * NC;
        const uint32_t bufR = (c & 1) ? smbB1 : smbB0;
        const uint32_t bufW = (c & 1) ? smbB0 : smbB1;

        CP_WAIT0();
        __syncthreads();

        if (c < NCH - 1) {
            const int ncb = cb + NC;
            #pragma unroll
            for (int it = 0; it < 4; ++it) {
                const int task = tid + it * 256;
                const int col = task >> 3, part = task & 7;
                cp16(bufW + (uint32_t)(col * WB + part * 4) * 4,
                     g_ebH + (size_t)(ncb + col) * 32 + part * 4);
            }
            CP_COMMIT();
        }

        // acc init = -0.5*||e||^2
        float acc[2][4][4];
        #pragma unroll
        for (int nf = 0; nf < 4; nf++) {
            const int cl = cb + wn * 32 + nf * 8 + 2 * q;
            const float e0 = -0.5f * __ldg(g_en + cl);
            const float e1 = -0.5f * __ldg(g_en + cl + 1);
            #pragma unroll
            for (int mf = 0; mf < 2; mf++) {
                acc[mf][nf][0] = e0; acc[mf][nf][1] = e1;
                acc[mf][nf][2] = e0; acc[mf][nf][3] = e1;
            }
        }

        // hi*hi: 4 K16 slices, A from registers
        #pragma unroll
        for (int s = 0; s < 4; s++) {
            const uint32_t aw = (uint32_t)(8 * s) * 4;
            uint32_t B0[4], B1[4];
            ldm4(B0, bufR + bOff0 + aw);
            ldm4(B1, bufR + bOff1 + aw);
            #pragma unroll
            for (int mf = 0; mf < 2; mf++) {
                mma_f16(acc[mf][0], Af[s][mf], &B0[0]);
                mma_f16(acc[mf][1], Af[s][mf], &B0[2]);
                mma_f16(acc[mf][2], Af[s][mf], &B1[0]);
                mma_f16(acc[mf][3], Af[s][mf], &B1[2]);
            }
        }

        // top-2 update: 1 LOP3 pack + 3 min/max per value
        #pragma unroll
        for (int nf = 0; nf < 4; nf++) {
            const int base = cb + wn * 32 + nf * 8 + 2 * q;
            const uint32_t inv0 = (uint32_t)(1023 - base);
            const uint32_t inv1 = (uint32_t)(1022 - base);
            #pragma unroll
            for (int mf = 0; mf < 2; mf++) {
                #pragma unroll
                for (int v = 0; v < 4; v++) {
                    const float key = __uint_as_float(
                        (__float_as_uint(acc[mf][nf][v]) & 0xFFFFFC00u)
                        | ((v & 1) ? inv1 : inv0));
                    const int sl = 2 * mf + (v >> 1);
                    const float lo = fminf(key, b1k[sl]);
                    b1k[sl] = fmaxf(key, b1k[sl]);
                    b2k[sl] = fmaxf(b2k[sl], lo);
                }
            }
        }
    }
    __syncthreads();   // B buffers dead; sKey overlay safe

    // ---- write top-2 keys per slot ----
    {
        const int slot = wn * 4 + q;
        #pragma unroll
        for (int i = 0; i < 4; i++) {
            const int mf = i >> 1, half = i & 1;
            const int r = wm * 32 + mf * 16 + g + half * 8;
            sKey[r * 32 + slot * 2]     = b1k[i];
            sKey[r * 32 + slot * 2 + 1] = b2k[i];
        }
    }
    __syncthreads();

    // ---- epilogue: 4 threads/row ----
    {
        const int r = tid >> 2, part = tid & 3;
        const uint32_t mask4 = 0xFu << (lane & 28);

        float kbuf[8];
        const float* krow = sKey + r * 32 + part * 8;
        #pragma unroll
        for (int t = 0; t < 8; t++) kbuf[t] = krow[t];
        float kmax = kbuf[0];
        #pragma unroll
        for (int t = 1; t < 8; t++) kmax = fmaxf(kmax, kbuf[t]);
        kmax = fmaxf(kmax, __shfl_xor_sync(mask4, kmax, 1));
        kmax = fmaxf(kmax, __shfl_xor_sync(mask4, kmax, 2));
        const float sbest = __uint_as_float(__float_as_uint(kmax) & 0xFFFFFC00u);

        const float nh = sqrtf(sNh[r * 4] + sNh[r * 4 + 1] + sNh[r * 4 + 2] + sNh[r * 4 + 3]);
        const float nl = sqrtf(sNl[r * 4] + sNl[r * 4 + 1] + sNl[r * 4 + 2] + sNl[r * 4 + 3]);
        const float maxE  = sqrtf(__int_as_float(g_maxE2i));
        const float maxEl = sqrtf(__int_as_float(g_maxEl2i));
        const float thr = sbest - 2.0f * (nh * maxEl + nl * maxE + 2e-3f)
                        - fabsf(sbest) * 1e-3f - 1e-3f;

        float4 xv4[4];
        {
            const float4* xr = (const float4*)(x + (size_t)(rowBase + r) * DIM + part * 16);
            #pragma unroll
            for (int i = 0; i < 4; i++) xv4[i] = xr[i];
        }
        const float* xvf = (const float*)xv4;

        float bestEx = -3.4e38f;
        int   bj = 0;
        #pragma unroll
        for (int t = 0; t < 8; t++) {
            unsigned m = __ballot_sync(mask4, kbuf[t] >= thr);
            while (m) {
                const int li = __ffs(m) - 1; m &= m - 1;
                const float kf = __shfl_sync(mask4, kbuf[t], li);
                const int j = 1023 - (int)(__float_as_uint(kf) & 1023u);
                const float* et = g_ebT + (size_t)j * 64 + part * 16;
                float p = 0.0f;
                #pragma unroll
                for (int kk = 0; kk < 16; kk++) p = fmaf(xvf[kk], __ldg(et + kk), p);
                p += __shfl_xor_sync(mask4, p, 1);
                p += __shfl_xor_sync(mask4, p, 2);
                const float s = p - 0.5f * __ldg(g_en + j);
                if (s > bestEx || (s == bestEx && j < bj)) { bestEx = s; bj = j; }
            }
        }

        if (part == 0) {
            out[OFF_IND + rowBase + r] = (float)bj;
            atomicAdd(&g_countP[grp][bj], 1.0f);
        }

        float dsum = 0.0f;
        const float4* ecol4 = (const float4*)(g_ebT + (size_t)bj * 64 + part * 16);
        float4* qout4 = (float4*)(out + (size_t)(rowBase + r) * DIM + part * 16);
        float* esum = &g_esumP[grp][bj * 64 + part * 16];
        #pragma unroll
        for (int b = 0; b < 4; b++) {
            const float4 qv = ecol4[b];
            const float4 xb = xv4[b];
            float d0 = qv.x - xb.x, d1 = qv.y - xb.y;
            float d2 = qv.z - xb.z, d3 = qv.w - xb.w;
            dsum = fmaf(d0, d0, fmaf(d1, d1, fmaf(d2, d2, fmaf(d3, d3, dsum))));
            qout4[b] = qv;
            atomicAdd(esum + 4 * b,     xb.x);
            atomicAdd(esum + 4 * b + 1, xb.y);
            atomicAdd(esum + 4 * b + 2, xb.z);
            atomicAdd(esum + 4 * b + 3, xb.w);
        }
        __syncwarp();
        #pragma unroll
        for (int o = 16; o; o >>= 1) dsum += __shfl_xor_sync(0xffffffffu, dsum, o);
        if (lane == 0) atomicAdd(&g_diff, (double)dsum);
    }
}

// ------------------------------------------------------------------
__global__ void k2a(const float* __restrict__ cluster_size, float* __restrict__ out)
{
    __shared__ double ssum[32];
    int j = threadIdx.x;

    float cnt = 0.0f;
    #pragma unroll
    for (int p = 0; p < NGRP; p++) { cnt += g_countP[p][j]; g_countP[p][j] = 0.0f; }

    float ncs = DECAYF * cluster_size[j] + ONE_M_D * cnt;
    out[OFF_NCS + j] = ncs;

    double v = (double)ncs;
    #pragma unroll
    for (int o = 16; o; o >>= 1) v += __shfl_xor_sync(0xffffffffu, v, o);
    if ((j & 31) == 0) ssum[j >> 5] = v;
    __syncthreads();
    if (j < 32) {
        double t = ssum[j];
        #pragma unroll
        for (int o = 16; o; o >>= 1) t += __shfl_xor_sync(0xffffffffu, t, o);
        if (j == 0) {
            g_n = (float)t;
            out[OFF_DIFF] = (float)(g_diff * (1.0 / 8388608.0));
            g_diff = 0.0;
        }
    }
}

// k2b: 256 blocks x 256 threads; block -> (k, j-quarter)
__global__ void k2b(const float* __restrict__ embed_avg, float* __restrict__ out)
{
    const int k = blockIdx.x >> 2;
    const int j = (blockIdx.x & 3) * 256 + threadIdx.x;
    const float n = g_n;
    const float ncs = out[OFF_NCS + j];
    const float cs = (ncs + EPSF) / (n + (float)NE * EPSF) * n;
    float es = 0.0f;
    #pragma unroll
    for (int p = 0; p < NGRP; p++) { es += g_esumP[p][j * 64 + k]; g_esumP[p][j * 64 + k] = 0.0f; }
    const float ea = DECAYF * embed_avg[k * NE + j] + ONE_M_D * es;
    out[OFF_NEA + k * NE + j] = ea;
    out[OFF_NE  + k * NE + j] = ea / cs;
}

__global__ void kdummy() {}

// ------------------------------------------------------------------
extern "C" void kernel_launch(void* const* d_in, const int* in_sizes, int n_in,
                              void* d_out, int out_size) {
    const float* x            = (const float*)d_in[0];
    const float* embed        = (const float*)d_in[1];
    const float* cluster_size = (const float*)d_in[2];
    const float* embed_avg    = (const float*)d_in[3];
    float* out = (float*)d_out;

    cudaFuncSetAttribute(k1_main, cudaFuncAttributeMaxDynamicSharedMemorySize, SMEM_BYTES);

    // keep k1 at launch index 3 so the ncu window lands on it
    kdummy<<<1, 32>>>();
    kdummy<<<1, 32>>>();
    k0pre<<<8, 128>>>(embed);
    k1_main<<<NROWS / BM, 256, SMEM_BYTES>>>(x, embed, out);
    k2a<<<1, 1024>>>(cluster_size, out);
    k2b<<<256, 256>>>(embed_avg, out);
}

// round 16
// speedup vs baseline: 1.0748x; 1.0748x over previous
#include <cuda_runtime.h>
#include <cuda_fp16.h>
#include <cstdint>

#define NROWS   131072
#define DIM     64
#define NE      1024
#define DECAYF  0.99f
#define ONE_M_D 0.01f
#define EPSF    1e-5f

#define OFF_Q    0
#define OFF_DIFF 8388608
#define OFF_IND  8388609
#define OFF_NCS  8519681
#define OFF_NEA  8520705
#define OFF_NE   8586241

#define NGRP 16

// device scratch (statically zero-initialized; k2a/k2b re-zero after use)
__device__ float    g_countP[NGRP][NE];
__device__ float    g_esumP[NGRP][NE * DIM];
__device__ double   g_diff;
__device__ float    g_n;
__device__ uint32_t g_ebH[NE * 32];   // fp16-hi of embed, col-major
__device__ float    g_ebT[NE * DIM];  // transposed fp32 embed [j][k]
__device__ float    g_en[NE];         // ||e_j||^2
__device__ int      g_maxE2i;
__device__ int      g_maxEl2i;

// ------------------------------------------------------------------
__device__ __forceinline__ void mma_f16(float* c, const uint32_t* a, const uint32_t* b) {
    asm volatile(
        "mma.sync.aligned.m16n8k16.row.col.f32.f16.f16.f32 "
        "{%0,%1,%2,%3}, {%4,%5,%6,%7}, {%8,%9}, {%0,%1,%2,%3};"
        : "+f"(c[0]), "+f"(c[1]), "+f"(c[2]), "+f"(c[3])
        : "r"(a[0]), "r"(a[1]), "r"(a[2]), "r"(a[3]),
          "r"(b[0]), "r"(b[1]));
}
__device__ __forceinline__ void ldm4(uint32_t* r, uint32_t addr) {
    asm volatile("ldmatrix.sync.aligned.m8n8.x4.shared.b16 {%0,%1,%2,%3}, [%4];"
        : "=r"(r[0]), "=r"(r[1]), "=r"(r[2]), "=r"(r[3]) : "r"(addr));
}
__device__ __forceinline__ uint32_t h2(float a, float b) {
    __half2 h = __floats2half2_rn(a, b);
    return *(uint32_t*)&h;
}
__device__ __forceinline__ uint32_t smem_u32(const void* p) {
    uint32_t a;
    asm("{ .reg .u64 t; cvta.to.shared.u64 t, %1; cvt.u32.u64 %0, t; }" : "=r"(a) : "l"(p));
    return a;
}
__device__ __forceinline__ void cp16(uint32_t s, const void* g) {
    asm volatile("cp.async.cg.shared.global [%0], [%1], 16;" :: "r"(s), "l"(g));
}
#define CP_COMMIT() asm volatile("cp.async.commit_group;" ::: "memory")
#define CP_WAIT0()  asm volatile("cp.async.wait_group 0;" ::: "memory")

// ------------------------------------------------------------------
// SMEM (32-bit words)
#define WA 68
#define WB 36
#define SM_A    0
#define SM_B0   (64 * WA)                  // 4352
#define SM_B1   (SM_B0 + 128 * WB)         // 8960
#define SM_KEY  SM_B0
#define SM_NORM (SM_B1 + 128 * WB)         // 13568
#define SMEM_WORDS (SM_NORM + 512)         // 14080
#define SMEM_BYTES (SMEM_WORDS * 4)        // 56320

#define BM 64
#define NC 128
#define NCH 8

// ------------------------------------------------------------------
__global__ void k0pre(const float* __restrict__ embed) {
    const int j = blockIdx.x * 128 + threadIdx.x;   // 1024 threads
    float en = 0.0f, el2 = 0.0f;
    #pragma unroll 8
    for (int w = 0; w < 32; w++) {
        float v0 = embed[(2 * w) * NE + j];
        float v1 = embed[(2 * w + 1) * NE + j];
        en = fmaf(v0, v0, fmaf(v1, v1, en));
        uint32_t hw = h2(v0, v1);
        __half2 hh = *(__half2*)&hw;
        float2 f = __half22float2(hh);
        float l0 = v0 - f.x, l1 = v1 - f.y;
        el2 = fmaf(l0, l0, fmaf(l1, l1, el2));
        g_ebH[j * 32 + w] = hw;
        g_ebT[j * 64 + 2 * w]     = v0;
        g_ebT[j * 64 + 2 * w + 1] = v1;
    }
    g_en[j] = en;
    atomicMax(&g_maxE2i,  __float_as_int(en));
    atomicMax(&g_maxEl2i, __float_as_int(el2));
}

// ------------------------------------------------------------------
__global__ void __launch_bounds__(256, 3) k1_main(
    const float* __restrict__ x,
    const float* __restrict__ embed,
    float* __restrict__ out)
{
    extern __shared__ uint32_t smw[];
    uint32_t* As = smw + SM_A;
    float* sKey = (float*)(smw + SM_KEY);
    float* sNh = (float*)(smw + SM_NORM);
    float* sNl = (float*)(smw + SM_NORM + 256);
    const uint32_t smbA  = smem_u32(smw);
    const uint32_t smbB0 = smbA + SM_B0 * 4;
    const uint32_t smbB1 = smbA + SM_B1 * 4;

    const int tid  = threadIdx.x;
    const int wid  = tid >> 5;
    const int lane = tid & 31;
    const int g    = lane >> 2;
    const int q    = lane & 3;
    const int wm   = wid >> 2;
    const int wn   = wid & 3;
    const int rowBase = blockIdx.x * BM;
    const int grp = blockIdx.x & (NGRP - 1);

    // ---- prefetch B chunk 0 ----
    #pragma unroll
    for (int it = 0; it < 4; ++it) {
        const int task = tid + it * 256;
        const int col = task >> 3, part = task & 7;
        cp16(smbB0 + (uint32_t)(col * WB + part * 4) * 4,
             g_ebH + (size_t)col * 32 + part * 4);
    }
    CP_COMMIT();

    // ---- load A: fp16 split + norm partials (4 thr/row) ----
    {
        const int r = tid >> 2, quarter = tid & 3;
        const float4* xg = (const float4*)(x + (size_t)(rowBase + r) * DIM) + quarter * 4;
        uint32_t* dA = As + r * WA + quarter * 8;
        float nh = 0.0f, nl = 0.0f;
        #pragma unroll
        for (int i = 0; i < 4; i++) {
            float4 v = xg[i];
            uint32_t hxy = h2(v.x, v.y), hzw = h2(v.z, v.w);
            __half2 hh0 = *(__half2*)&hxy, hh1 = *(__half2*)&hzw;
            float2 f0 = __half22float2(hh0), f1 = __half22float2(hh1);
            float l00 = v.x - f0.x, l01 = v.y - f0.y;
            float l10 = v.z - f1.x, l11 = v.w - f1.y;
            nh = fmaf(f0.x, f0.x, fmaf(f0.y, f0.y, fmaf(f1.x, f1.x, fmaf(f1.y, f1.y, nh))));
            nl = fmaf(l00, l00, fmaf(l01, l01, fmaf(l10, l10, fmaf(l11, l11, nl))));
            dA[2 * i]          = hxy;
            dA[2 * i + 1]      = hzw;
            dA[32 + 2 * i]     = h2(l00, l01);
            dA[32 + 2 * i + 1] = h2(l10, l11);
        }
        sNh[tid] = nh;
        sNl[tid] = nl;
    }

    // per-lane ldmatrix addresses
    const int r8  = lane & 7;
    const int sel = lane >> 3;
    uint32_t aAddr[2];
    #pragma unroll
    for (int mf = 0; mf < 2; mf++) {
        const int row = wm * 32 + mf * 16 + r8 + (sel & 1) * 8;
        aAddr[mf] = smbA + (uint32_t)(row * WA + (sel >> 1) * 4) * 4;
    }
    const uint32_t bOff0 = (uint32_t)((wn * 32 + r8 + (sel >> 1) * 8) * WB + (sel & 1) * 4) * 4;
    const uint32_t bOff1 = bOff0 + (uint32_t)(16 * WB) * 4;

    // float-packed top-2 keys per slot (index in low 10 mantissa bits)
    float b1k[4], b2k[4];
    #pragma unroll
    for (int i = 0; i < 4; i++) { b1k[i] = -3.4e38f; b2k[i] = -3.4e38f; }

    for (int c = 0; c < NCH; c++) {
        const int cb = c * NC;
        const uint32_t bufR = (c & 1) ? smbB1 : smbB0;
        const uint32_t bufW = (c & 1) ? smbB0 : smbB1;

        CP_WAIT0();
        __syncthreads();

        if (c < NCH - 1) {
            const int ncb = cb + NC;
            #pragma unroll
            for (int it = 0; it < 4; ++it) {
                const int task = tid + it * 256;
                const int col = task >> 3, part = task & 7;
                cp16(bufW + (uint32_t)(col * WB + part * 4) * 4,
                     g_ebH + (size_t)(ncb + col) * 32 + part * 4);
            }
            CP_COMMIT();
        }

        // acc init = -0.5*||e||^2
        float acc[2][4][4];
        #pragma unroll
        for (int nf = 0; nf < 4; nf++) {
            const int cl = cb + wn * 32 + nf * 8 + 2 * q;
            const float e0 = -0.5f * __ldg(g_en + cl);
            const float e1 = -0.5f * __ldg(g_en + cl + 1);
            #pragma unroll
            for (int mf = 0; mf < 2; mf++) {
                acc[mf][nf][0] = e0; acc[mf][nf][1] = e1;
                acc[mf][nf][2] = e0; acc[mf][nf][3] = e1;
            }
        }

        // hi*hi: 4 K16 slices
        #pragma unroll
        for (int s = 0; s < 4; s++) {
            const uint32_t aw = (uint32_t)(8 * s) * 4;
            uint32_t B0[4], B1[4];
            ldm4(B0, bufR + bOff0 + aw);
            ldm4(B1, bufR + bOff1 + aw);
            #pragma unroll
            for (int mf = 0; mf < 2; mf++) {
                uint32_t A[4];
                ldm4(A, aAddr[mf] + aw);
                mma_f16(acc[mf][0], A, &B0[0]);
                mma_f16(acc[mf][1], A, &B0[2]);
                mma_f16(acc[mf][2], A, &B1[0]);
                mma_f16(acc[mf][3], A, &B1[2]);
            }
        }

        // top-2 update: 1 LOP3 pack + 3 min/max per value
        #pragma unroll
        for (int nf = 0; nf < 4; nf++) {
            const int base = cb + wn * 32 + nf * 8 + 2 * q;
            const uint32_t inv0 = (uint32_t)(1023 - base);
            const uint32_t inv1 = (uint32_t)(1022 - base);
            #pragma unroll
            for (int mf = 0; mf < 2; mf++) {
                #pragma unroll
                for (int v = 0; v < 4; v++) {
                    const float key = __uint_as_float(
                        (__float_as_uint(acc[mf][nf][v]) & 0xFFFFFC00u)
                        | ((v & 1) ? inv1 : inv0));
                    const int sl = 2 * mf + (v >> 1);
                    const float lo = fminf(key, b1k[sl]);
                    b1k[sl] = fmaxf(key, b1k[sl]);
                    b2k[sl] = fmaxf(b2k[sl], lo);
                }
            }
        }
    }
    __syncthreads();   // B buffers dead; sKey overlay safe

    // ---- write top-2 keys per slot ----
    {
        const int slot = wn * 4 + q;
        #pragma unroll
        for (int i = 0; i < 4; i++) {
            const int mf = i >> 1, half = i & 1;
            const int r = wm * 32 + mf * 16 + g + half * 8;
            sKey[r * 32 + slot * 2]     = b1k[i];
            sKey[r * 32 + slot * 2 + 1] = b2k[i];
        }
    }
    __syncthreads();

    // ---- epilogue: 4 threads/row ----
    {
        const int r = tid >> 2, part = tid & 3;
        const uint32_t mask4 = 0xFu << (lane & 28);

        // lane-split key scan (floats)
        float kbuf[8];
        const float* krow = sKey + r * 32 + part * 8;
        #pragma unroll
        for (int t = 0; t < 8; t++) kbuf[t] = krow[t];
        float kmax = kbuf[0];
        #pragma unroll
        for (int t = 1; t < 8; t++) kmax = fmaxf(kmax, kbuf[t]);
        kmax = fmaxf(kmax, __shfl_xor_sync(mask4, kmax, 1));
        kmax = fmaxf(kmax, __shfl_xor_sync(mask4, kmax, 2));
        const float sbest = __uint_as_float(__float_as_uint(kmax) & 0xFFFFFC00u);

        const float nh = sqrtf(sNh[r * 4] + sNh[r * 4 + 1] + sNh[r * 4 + 2] + sNh[r * 4 + 3]);
        const float nl = sqrtf(sNl[r * 4] + sNl[r * 4 + 1] + sNl[r * 4 + 2] + sNl[r * 4 + 3]);
        const float maxE  = sqrtf(__int_as_float(g_maxE2i));
        const float maxEl = sqrtf(__int_as_float(g_maxEl2i));
        const float thr = sbest - 2.0f * (nh * maxEl + nl * maxE + 2e-3f)
                        - fabsf(sbest) * 1e-3f - 1e-3f;   // + key quantization slack

        // exact x row (registers, fp32)
        float4 xv4[4];
        {
            const float4* xr = (const float4*)(x + (size_t)(rowBase + r) * DIM + part * 16);
            #pragma unroll
            for (int i = 0; i < 4; i++) xv4[i] = xr[i];
        }
        const float* xvf = (const float*)xv4;

        // ballot-enumerated exact rescore over g_ebT
        float bestEx = -3.4e38f;
        int   bj = 0;
        #pragma unroll
        for (int t = 0; t < 8; t++) {
            unsigned m = __ballot_sync(mask4, kbuf[t] >= thr);
            while (m) {
                const int li = __ffs(m) - 1; m &= m - 1;
                const float kf = __shfl_sync(mask4, kbuf[t], li);
                const int j = 1023 - (int)(__float_as_uint(kf) & 1023u);
                const float* et = g_ebT + (size_t)j * 64 + part * 16;
                float p = 0.0f;
                #pragma unroll
                for (int kk = 0; kk < 16; kk++) p = fmaf(xvf[kk], __ldg(et + kk), p);
                p += __shfl_xor_sync(mask4, p, 1);
                p += __shfl_xor_sync(mask4, p, 2);
                const float s = p - 0.5f * __ldg(g_en + j);
                if (s > bestEx || (s == bestEx && j < bj)) { bestEx = s; bj = j; }
            }
        }

        if (part == 0) {
            out[OFF_IND + rowBase + r] = (float)bj;
            atomicAdd(&g_countP[grp][bj], 1.0f);
        }

        // gather Q from g_ebT, diff, privatized esum atomics (exact x)
        float dsum = 0.0f;
        const float4* ecol4 = (const float4*)(g_ebT + (size_t)bj * 64 + part * 16);
        float4* qout4 = (float4*)(out + (size_t)(rowBase + r) * DIM + part * 16);
        float* esum = &g_esumP[grp][bj * 64 + part * 16];
        #pragma unroll
        for (int b = 0; b < 4; b++) {
            const float4 qv = ecol4[b];
            const float4 xb = xv4[b];
            float d0 = qv.x - xb.x, d1 = qv.y - xb.y;
            float d2 = qv.z - xb.z, d3 = qv.w - xb.w;
            dsum = fmaf(d0, d0, fmaf(d1, d1, fmaf(d2, d2, fmaf(d3, d3, dsum))));
            qout4[b] = qv;
            atomicAdd(esum + 4 * b,     xb.x);
            atomicAdd(esum + 4 * b + 1, xb.y);
            atomicAdd(esum + 4 * b + 2, xb.z);
            atomicAdd(esum + 4 * b + 3, xb.w);
        }
        __syncwarp();
        #pragma unroll
        for (int o = 16; o; o >>= 1) dsum += __shfl_xor_sync(0xffffffffu, dsum, o);
        if (lane == 0) atomicAdd(&g_diff, (double)dsum);
    }
}

// ------------------------------------------------------------------
__global__ void k2a(const float* __restrict__ cluster_size, float* __restrict__ out)
{
    __shared__ double ssum[32];
    int j = threadIdx.x;

    float cnt = 0.0f;
    #pragma unroll
    for (int p = 0; p < NGRP; p++) { cnt += g_countP[p][j]; g_countP[p][j] = 0.0f; }

    float ncs = DECAYF * cluster_size[j] + ONE_M_D * cnt;
    out[OFF_NCS + j] = ncs;

    double v = (double)ncs;
    #pragma unroll
    for (int o = 16; o; o >>= 1) v += __shfl_xor_sync(0xffffffffu, v, o);
    if ((j & 31) == 0) ssum[j >> 5] = v;
    __syncthreads();
    if (j < 32) {
        double t = ssum[j];
        #pragma unroll
        for (int o = 16; o; o >>= 1) t += __shfl_xor_sync(0xffffffffu, t, o);
        if (j == 0) {
            g_n = (float)t;
            out[OFF_DIFF] = (float)(g_diff * (1.0 / 8388608.0));
            g_diff = 0.0;
        }
    }
}

// k2b: 256 blocks x 256 threads; block -> (k, j-quarter)
__global__ void k2b(const float* __restrict__ embed_avg, float* __restrict__ out)
{
    const int k = blockIdx.x >> 2;
    const int j = (blockIdx.x & 3) * 256 + threadIdx.x;
    const float n = g_n;
    const float ncs = out[OFF_NCS + j];
    const float cs = (ncs + EPSF) / (n + (float)NE * EPSF) * n;
    float es = 0.0f;
    #pragma unroll
    for (int p = 0; p < NGRP; p++) { es += g_esumP[p][j * 64 + k]; g_esumP[p][j * 64 + k] = 0.0f; }
    const float ea = DECAYF * embed_avg[k * NE + j] + ONE_M_D * es;
    out[OFF_NEA + k * NE + j] = ea;
    out[OFF_NE  + k * NE + j] = ea / cs;
}

__global__ void kdummy() {}

// ------------------------------------------------------------------
extern "C" void kernel_launch(void* const* d_in, const int* in_sizes, int n_in,
                              void* d_out, int out_size) {
    const float* x            = (const float*)d_in[0];
    const float* embed        = (const float*)d_in[1];
    const float* cluster_size = (const float*)d_in[2];
    const float* embed_avg    = (const float*)d_in[3];
    float* out = (float*)d_out;

    cudaFuncSetAttribute(k1_main, cudaFuncAttributeMaxDynamicSharedMemorySize, SMEM_BYTES);

    // keep k1 at launch index 3 so the ncu window lands on it
    kdummy<<<1, 32>>>();
    kdummy<<<1, 32>>>();
    k0pre<<<8, 128>>>(embed);
    k1_main<<<NROWS / BM, 256, SMEM_BYTES>>>(x, embed, out);
    k2a<<<1, 1024>>>(cluster_size, out);
    k2b<<<256, 256>>>(embed_avg, out);
}